// round 12
// baseline (speedup 1.0000x reference)
#include <cuda_runtime.h>
#include <cuda_fp16.h>
#include <cstdint>
#include <math.h>

#define B_  2
#define T_  2048
#define C_  1024
#define H_  16
#define D_  64
#define BT_ 4096

// ---------------- scratch (allocation-free contract: __device__ globals) ----
__device__ __half g_qh[BT_ * C_];          // Q fp16 (rope+scale*log2e applied)
__device__ __half g_kh[BT_ * C_];          // K fp16 (rope applied)
__device__ __half g_vt[B_ * H_ * D_ * T_]; // V fp16 transposed [b][h][d][t]
__device__ __half g_atth[BT_ * C_];        // attention output, fp16
__device__ __half g_xh[BT_ * C_];          // x pre-rounded to fp16
__device__ __half g_wh[4 * C_ * C_];       // wq,wk,wv,wo pre-rounded to fp16

// ---------------- helpers ---------------------------------------------------
__device__ __forceinline__ uint32_t smem_u32(const void* p) {
    uint32_t a;
    asm("{ .reg .u64 t; cvta.to.shared.u64 t, %1; cvt.u32.u64 %0, t; }"
        : "=r"(a) : "l"(p));
    return a;
}

__device__ __forceinline__ float ex2f(float x) {
    float r;
    asm("ex2.approx.ftz.f32 %0, %1;" : "=f"(r) : "f"(x));
    return r;
}

__device__ __forceinline__ uint32_t h2ex2(uint32_t x) {
    uint32_t r;
    asm("ex2.approx.f16x2 %0, %1;" : "=r"(r) : "r"(x));
    return r;
}

__device__ __forceinline__ uint32_t packh2(float lo, float hi) {
    __half2 t = __floats2half2_rn(lo, hi);
    return *(uint32_t*)&t;
}

__device__ __forceinline__ float2 unpackh2(uint32_t u) {
    __half2 t = *(__half2*)&u;
    return __half22float2(t);
}

__device__ __forceinline__ void mma_f16r(float c[4], uint32_t a0, uint32_t a1,
                                         uint32_t a2, uint32_t a3,
                                         uint32_t b0, uint32_t b1) {
    asm volatile(
        "mma.sync.aligned.m16n8k16.row.col.f32.f16.f16.f32 "
        "{%0,%1,%2,%3}, {%4,%5,%6,%7}, {%8,%9}, {%0,%1,%2,%3};\n"
        : "+f"(c[0]), "+f"(c[1]), "+f"(c[2]), "+f"(c[3])
        : "r"(a0), "r"(a1), "r"(a2), "r"(a3), "r"(b0), "r"(b1));
}

#define LDSM_X4(r0, r1, r2, r3, addr) \
    asm volatile("ldmatrix.sync.aligned.m8n8.x4.shared.b16 {%0,%1,%2,%3}, [%4];" \
                 : "=r"(r0), "=r"(r1), "=r"(r2), "=r"(r3) : "r"(addr))

__device__ __forceinline__ void cpa16(uint32_t saddr, const void* g) {
    asm volatile("cp.async.cg.shared.global [%0], [%1], 16;"
                 :: "r"(saddr), "l"(g) : "memory");
}
#define CP_COMMIT() asm volatile("cp.async.commit_group;" ::: "memory")
#define CP_WAIT1()  asm volatile("cp.async.wait_group 1;" ::: "memory")
#define CP_WAIT0()  asm volatile("cp.async.wait_group 0;" ::: "memory")

__device__ __forceinline__ void rope2(float& e, float& o, float t,
                                      float f0, float f1, float scale) {
    float s0, c0, s1, c1;
    sincosf(t * f0, &s0, &c0);
    sincosf(t * f1, &s1, &c1);
    float en = (e * c0 - o * s0) * scale;
    float on = (o * c1 + e * s1) * scale;
    e = en; o = on;
}

#define ROPE_LG 0.41524103786091404f   // log2(10000)*2/64
#define QSCALE  0.18033688011112042f   // 0.125 * log2(e)

// ---------------- fp16 pre-convert kernels ---------------------------------
__global__ __launch_bounds__(256) void convx_kernel(const float* __restrict__ s)
{
    int i = blockIdx.x * 256 + threadIdx.x;
    float4 v0 = ((const float4*)s)[2 * i];
    float4 v1 = ((const float4*)s)[2 * i + 1];
    uint4 u;
    u.x = packh2(v0.x, v0.y); u.y = packh2(v0.z, v0.w);
    u.z = packh2(v1.x, v1.y); u.w = packh2(v1.z, v1.w);
    ((uint4*)g_xh)[i] = u;
}

__global__ __launch_bounds__(256) void convw_kernel(
    const float* __restrict__ wq, const float* __restrict__ wk,
    const float* __restrict__ wv, const float* __restrict__ wo)
{
    const float* src;
    int z = blockIdx.y;
    if (z == 0)      src = wq;
    else if (z == 1) src = wk;
    else if (z == 2) src = wv;
    else             src = wo;
    int i = blockIdx.x * 256 + threadIdx.x;
    float4 v0 = ((const float4*)src)[2 * i];
    float4 v1 = ((const float4*)src)[2 * i + 1];
    uint4 u;
    u.x = packh2(v0.x, v0.y); u.y = packh2(v0.z, v0.w);
    u.z = packh2(v1.x, v1.y); u.w = packh2(v1.z, v1.w);
    ((uint4*)(g_wh + (size_t)z * C_ * C_))[i] = u;
}

// ---------------- fp16 GEMM: C[M,N] = A[M,K] @ W[N,K]^T + bias --------------
// block 128x128, BK=64 halfs, 256 threads = 8 warps (warp tile 32m x 64n),
// m16n8k16, fragments via ldmatrix.x4 (stride 36 words: conflict-free).
#define GH_STR 36
#define GH_STAGE_W (2 * 128 * GH_STR)
#define GH_SMEM_BYTES (2 * GH_STAGE_W * 4)

__device__ __forceinline__ void gemm_f16_body(
    const __half* __restrict__ A, const __half* __restrict__ W,
    const float* __restrict__ bias, float* __restrict__ Cm,
    int bx, int by, int mode)
{
    extern __shared__ uint32_t gsm[];

    const int K = C_, N = C_;
    const int tid  = threadIdx.x;
    const int warp = tid >> 5;
    const int lane = tid & 31;
    const int g    = lane >> 2;
    const int tg   = lane & 3;
    const int m0   = (warp & 3) * 32;
    const int n0   = (warp >> 2) * 64;
    const int bm   = by * 128;
    const int bn   = bx * 128;

    const uint32_t smem_base = smem_u32(gsm);
    const __half* Ap = A + (size_t)bm * K;
    const __half* Wp = W + (size_t)bn * K;

    const int arow = (lane & 7) + ((lane >> 3) & 1) * 8;
    const int akof = (lane >> 4) * 4;
    const int brow = lane & 7;
    const int bkof = ((lane >> 3) & 1) * 4;
    const int bns  = (lane >> 4) * 8;

    float acc[2][8][4];
#pragma unroll
    for (int mt = 0; mt < 2; ++mt)
#pragma unroll
        for (int nt = 0; nt < 8; ++nt)
#pragma unroll
            for (int i = 0; i < 4; ++i) acc[mt][nt][i] = 0.f;

    auto issue = [&](int kb) {
        const int buf = kb & 1;
        uint32_t sa = smem_base + (buf * GH_STAGE_W) * 4;
        uint32_t sb = sa + 128 * GH_STR * 4;
        const __half* Ak = Ap + kb * 64;
        const __half* Wk = Wp + kb * 64;
#pragma unroll
        for (int i = 0; i < 4; ++i) {
            int id = tid + (i << 8);
            int r  = id >> 3;
            int c  = id & 7;
            cpa16(sa + (r * GH_STR + c * 4) * 4, Ak + (size_t)r * K + c * 8);
            cpa16(sb + (r * GH_STR + c * 4) * 4, Wk + (size_t)r * K + c * 8);
        }
    };

    issue(0);
    CP_COMMIT();

    const int NKB = K / 64;   // 16
    for (int kb = 0; kb < NKB; ++kb) {
        if (kb + 1 < NKB) {
            issue(kb + 1);
            CP_COMMIT();
            CP_WAIT1();
        } else {
            CP_WAIT0();
        }
        __syncthreads();

        const uint32_t As = smem_base + ((kb & 1) * GH_STAGE_W) * 4;
        const uint32_t Bs = As + 128 * GH_STR * 4;
        const uint32_t aAddr0 = As + ((m0 + arow) * GH_STR + akof) * 4;
        const uint32_t aAddr1 = As + ((m0 + 16 + arow) * GH_STR + akof) * 4;
        const uint32_t bAddr  = Bs + ((n0 + bns + brow) * GH_STR + bkof) * 4;

#pragma unroll
        for (int ks = 0; ks < 4; ++ks) {
            const int ko = ks * 8 * 4;
            uint32_t a[2][4], b[8][2];
            LDSM_X4(a[0][0], a[0][1], a[0][2], a[0][3], aAddr0 + ko);
            LDSM_X4(a[1][0], a[1][1], a[1][2], a[1][3], aAddr1 + ko);
#pragma unroll
            for (int ntp = 0; ntp < 4; ++ntp) {
                LDSM_X4(b[2 * ntp][0], b[2 * ntp][1],
                        b[2 * ntp + 1][0], b[2 * ntp + 1][1],
                        bAddr + (ntp * 16 * GH_STR) * 4 + ko);
            }
#pragma unroll
            for (int mt = 0; mt < 2; ++mt)
#pragma unroll
                for (int nt = 0; nt < 8; ++nt)
                    mma_f16r(acc[mt][nt], a[mt][0], a[mt][1], a[mt][2],
                             a[mt][3], b[nt][0], b[nt][1]);
        }
        __syncthreads();
    }

    // ---- epilogue ----------------------------------------------------------
    const bool do_rope = (mode == 1 || mode == 2);
    const float rscale = (mode == 1) ? QSCALE : 1.f;
#pragma unroll
    for (int nt = 0; nt < 8; ++nt) {
        int col = bn + n0 + nt * 8 + (tg << 1);
        float2 bv = *(const float2*)(bias + col);
        float f0 = 0.f, f1 = 0.f;
        if (do_rope) {
            int d0 = col & (D_ - 1);
            f0 = exp2f(-ROPE_LG * (float)(d0 & 31));
            f1 = exp2f(-ROPE_LG * (float)((d0 + 1) & 31));
        }
#pragma unroll
        for (int mt = 0; mt < 2; ++mt) {
            int row = bm + m0 + mt * 16 + g;
            float e0 = acc[mt][nt][0] + bv.x, o0 = acc[mt][nt][1] + bv.y;
            float e1 = acc[mt][nt][2] + bv.x, o1 = acc[mt][nt][3] + bv.y;
            if (do_rope) {
                rope2(e0, o0, (float)(row & (T_ - 1)), f0, f1, rscale);
                rope2(e1, o1, (float)((row + 8) & (T_ - 1)), f0, f1, rscale);
            }
            if (mode == 1 || mode == 2) {
                __half* dst = (mode == 1 ? g_qh : g_kh);
                *(__half2*)(dst + (size_t)row * N + col) =
                    __floats2half2_rn(e0, o0);
                *(__half2*)(dst + (size_t)(row + 8) * N + col) =
                    __floats2half2_rn(e1, o1);
            } else if (mode == 3) {
                int h = col >> 6, d = col & 63;
                int b = row >> 11;
                int t = row & (T_ - 1);
                __half* base = g_vt + ((size_t)(b * H_ + h) * D_) * T_;
                base[(size_t)d * T_ + t]            = __float2half_rn(e0);
                base[(size_t)(d + 1) * T_ + t]      = __float2half_rn(o0);
                base[(size_t)d * T_ + t + 8]        = __float2half_rn(e1);
                base[(size_t)(d + 1) * T_ + t + 8]  = __float2half_rn(o1);
            } else {
                *(float2*)(Cm + (size_t)row * N + col)       = make_float2(e0, o0);
                *(float2*)(Cm + (size_t)(row + 8) * N + col) = make_float2(e1, o1);
            }
        }
    }
}

__global__ __launch_bounds__(256, 2) void qkv_kernel(
    const float* __restrict__ bq, const float* __restrict__ bk,
    const float* __restrict__ bv)
{
    const float* bb; int mode;
    int z = blockIdx.z;
    if (z == 0)      { bb = bq; mode = 1; }
    else if (z == 1) { bb = bk; mode = 2; }
    else             { bb = bv; mode = 3; }
    gemm_f16_body(g_xh, g_wh + (size_t)z * C_ * C_, bb, nullptr,
                  blockIdx.x, blockIdx.y, mode);
}

__global__ __launch_bounds__(256, 2) void out_kernel(
    const float* __restrict__ bo, float* __restrict__ out)
{
    gemm_f16_body(g_atth, g_wh + (size_t)3 * C_ * C_, bo, out,
                  blockIdx.x, blockIdx.y, 0);
}

// ---------------- flash attention (fp16 m16n8k16, Br=256, Bc=64) -----------
// S(both mt) -> softmax(mt0) -> PV(mt0) -> softmax(mt1) -> PV(mt1):
// softmax of one half overlaps tensor work of the other. Exponentials via
// ex2.approx.f16x2 producing PV A-fragments directly (MUFU halved); row sums
// stay f32.
#define FSTR_W 36
#define F_STAGE_W (2 * 64 * FSTR_W)
#define FSMEM_BYTES (2 * F_STAGE_W * 4)

__global__ __launch_bounds__(256) void flash_kernel()
{
    extern __shared__ uint32_t sm[];

    const int bh = blockIdx.y;
    const int b  = bh >> 4;
    const int h  = bh & 15;
    const int t0 = blockIdx.x << 8;
    const int tid  = threadIdx.x;
    const int warp = tid >> 5;
    const int lane = tid & 31;
    const int g    = lane >> 2;
    const int tg   = lane & 3;
    const int m0   = warp << 5;

    const uint32_t smem_base = smem_u32(sm);
    const __half* Kg0 = g_kh + (size_t)(b * T_) * C_ + h * D_;
    const __half* Vt0 = g_vt + (size_t)(b * H_ + h) * D_ * T_;

    const int brow = lane & 7;
    const int bkof = ((lane >> 3) & 1) * 4;
    const int bns  = (lane >> 4) * 8;
    const uint32_t bOffB = ((bns + brow) * FSTR_W + bkof) * 4;

    auto issue_kv = [&](int kt) {
        const int buf = kt & 1;
        const uint32_t kb = smem_base + (buf * F_STAGE_W) * 4;
        const uint32_t vb = kb + 64 * FSTR_W * 4;
#pragma unroll
        for (int i = 0; i < 2; ++i) {
            int id = tid + (i << 8);
            int r  = id >> 3;
            int c  = id & 7;
            cpa16(kb + (r * FSTR_W + c * 4) * 4,
                  Kg0 + (size_t)(kt * 64 + r) * C_ + c * 8);
            cpa16(vb + (r * FSTR_W + c * 4) * 4,
                  Vt0 + (size_t)r * T_ + kt * 64 + c * 8);
        }
    };

    issue_kv(0);
    CP_COMMIT();

    // ---- Q fragments, kt-invariant, direct from gmem into registers ------
    uint32_t qa[4][2][4];
    const __half* Qg = g_qh + (size_t)(b * T_ + t0 + m0) * C_ + h * D_;
#pragma unroll
    for (int ks = 0; ks < 4; ++ks)
#pragma unroll
        for (int mt = 0; mt < 2; ++mt) {
            const __half* p0 = Qg + (size_t)(mt * 16 + g) * C_ + 16 * ks + 2 * tg;
            const __half* p1 = p0 + 8 * C_;
            qa[ks][mt][0] = *(const uint32_t*)p0;
            qa[ks][mt][1] = *(const uint32_t*)p1;
            qa[ks][mt][2] = *(const uint32_t*)(p0 + 8);
            qa[ks][mt][3] = *(const uint32_t*)(p1 + 8);
        }

    float oacc[2][8][4];
    float m_r[4], l_r[4];
#pragma unroll
    for (int mt = 0; mt < 2; ++mt)
#pragma unroll
        for (int nt = 0; nt < 8; ++nt)
#pragma unroll
            for (int i = 0; i < 4; ++i) oacc[mt][nt][i] = 0.f;
#pragma unroll
    for (int i = 0; i < 4; ++i) { m_r[i] = -1e30f; l_r[i] = 0.f; }

    const int NKT = T_ / 64;   // 32
    for (int kt = 0; kt < NKT; ++kt) {
        if (kt + 1 < NKT) {
            issue_kv(kt + 1);
            CP_COMMIT();
            CP_WAIT1();
        } else {
            CP_WAIT0();
        }
        __syncthreads();

        const uint32_t KbA = smem_base + ((kt & 1) * F_STAGE_W) * 4 + bOffB;
        const uint32_t VbA = KbA + 64 * FSTR_W * 4;

        // ---- S = Q @ K^T (log2-scaled), both halves ----
        float sacc[2][8][4];
#pragma unroll
        for (int mt = 0; mt < 2; ++mt)
#pragma unroll
            for (int nt = 0; nt < 8; ++nt)
#pragma unroll
                for (int i = 0; i < 4; ++i) sacc[mt][nt][i] = 0.f;

#pragma unroll
        for (int ks = 0; ks < 4; ++ks) {
            const int ko = ks * 8 * 4;
#pragma unroll
            for (int ntp = 0; ntp < 4; ++ntp) {
                uint32_t b00, b01, b10, b11;
                LDSM_X4(b00, b01, b10, b11,
                        KbA + (ntp * 16 * FSTR_W) * 4 + ko);
                mma_f16r(sacc[0][2 * ntp], qa[ks][0][0], qa[ks][0][1],
                         qa[ks][0][2], qa[ks][0][3], b00, b01);
                mma_f16r(sacc[1][2 * ntp], qa[ks][1][0], qa[ks][1][1],
                         qa[ks][1][2], qa[ks][1][3], b00, b01);
                mma_f16r(sacc[0][2 * ntp + 1], qa[ks][0][0], qa[ks][0][1],
                         qa[ks][0][2], qa[ks][0][3], b10, b11);
                mma_f16r(sacc[1][2 * ntp + 1], qa[ks][1][0], qa[ks][1][1],
                         qa[ks][1][2], qa[ks][1][3], b10, b11);
            }
        }

        // ---- per-half: softmax then PV (overlap across halves) ----
#pragma unroll
        for (int mt = 0; mt < 2; ++mt) {
            float mx0 = -1e30f, mx1 = -1e30f;
#pragma unroll
            for (int nt = 0; nt < 8; ++nt) {
                mx0 = fmaxf(mx0, fmaxf(sacc[mt][nt][0], sacc[mt][nt][1]));
                mx1 = fmaxf(mx1, fmaxf(sacc[mt][nt][2], sacc[mt][nt][3]));
            }
            mx0 = fmaxf(mx0, __shfl_xor_sync(0xffffffffu, mx0, 1));
            mx0 = fmaxf(mx0, __shfl_xor_sync(0xffffffffu, mx0, 2));
            mx1 = fmaxf(mx1, __shfl_xor_sync(0xffffffffu, mx1, 1));
            mx1 = fmaxf(mx1, __shfl_xor_sync(0xffffffffu, mx1, 2));

            float mn0 = fmaxf(m_r[mt * 2 + 0], mx0);
            float mn1 = fmaxf(m_r[mt * 2 + 1], mx1);
            float corr0 = ex2f(m_r[mt * 2 + 0] - mn0);
            float corr1 = ex2f(m_r[mt * 2 + 1] - mn1);

            // exponentials in f16x2, result IS the PV A-fragment word
            uint32_t pa[4][4];
            float rs0 = 0.f, rs1 = 0.f;
#pragma unroll
            for (int nt = 0; nt < 8; ++nt) {
                float d0 = sacc[mt][nt][0] - mn0;
                float d1 = sacc[mt][nt][1] - mn0;
                float d2 = sacc[mt][nt][2] - mn1;
                float d3 = sacc[mt][nt][3] - mn1;
                uint32_t e01 = h2ex2(packh2(d0, d1));
                uint32_t e23 = h2ex2(packh2(d2, d3));
                int ks = nt >> 1;
                int lo = (nt & 1) << 1;
                pa[ks][lo + 0] = e01;
                pa[ks][lo + 1] = e23;
                float2 f01 = unpackh2(e01);
                float2 f23 = unpackh2(e23);
                rs0 += f01.x + f01.y;
                rs1 += f23.x + f23.y;
            }
            rs0 += __shfl_xor_sync(0xffffffffu, rs0, 1);
            rs0 += __shfl_xor_sync(0xffffffffu, rs0, 2);
            rs1 += __shfl_xor_sync(0xffffffffu, rs1, 1);
            rs1 += __shfl_xor_sync(0xffffffffu, rs1, 2);

            l_r[mt * 2 + 0] = l_r[mt * 2 + 0] * corr0 + rs0;
            l_r[mt * 2 + 1] = l_r[mt * 2 + 1] * corr1 + rs1;
            m_r[mt * 2 + 0] = mn0;
            m_r[mt * 2 + 1] = mn1;

#pragma unroll
            for (int nt = 0; nt < 8; ++nt) {
                oacc[mt][nt][0] *= corr0; oacc[mt][nt][1] *= corr0;
                oacc[mt][nt][2] *= corr1; oacc[mt][nt][3] *= corr1;
            }

            // ---- O[mt] += P[mt] @ V ----
#pragma unroll
            for (int ks = 0; ks < 4; ++ks) {
                const int ko = ks * 8 * 4;
#pragma unroll
                for (int ntp = 0; ntp < 4; ++ntp) {
                    uint32_t b00, b01, b10, b11;
                    LDSM_X4(b00, b01, b10, b11,
                            VbA + (ntp * 16 * FSTR_W) * 4 + ko);
                    mma_f16r(oacc[mt][2 * ntp], pa[ks][0], pa[ks][1],
                             pa[ks][2], pa[ks][3], b00, b01);
                    mma_f16r(oacc[mt][2 * ntp + 1], pa[ks][0], pa[ks][1],
                             pa[ks][2], pa[ks][3], b10, b11);
                }
            }
        }
        __syncthreads();
    }

    // ---- epilogue: normalize, write fp16 concat-head ----------------------
    __half* Og = g_atth + (size_t)(b * T_ + t0) * C_ + h * D_;
#pragma unroll
    for (int mt = 0; mt < 2; ++mt) {
        float inv0 = 1.f / l_r[mt * 2 + 0];
        float inv1 = 1.f / l_r[mt * 2 + 1];
        int row = m0 + mt * 16 + g;
#pragma unroll
        for (int nt = 0; nt < 8; ++nt) {
            int col = (nt << 3) + (tg << 1);
            *(__half2*)(Og + (size_t)row * C_ + col) =
                __floats2half2_rn(oacc[mt][nt][0] * inv0,
                                  oacc[mt][nt][1] * inv0);
            *(__half2*)(Og + (size_t)(row + 8) * C_ + col) =
                __floats2half2_rn(oacc[mt][nt][2] * inv1,
                                  oacc[mt][nt][3] * inv1);
        }
    }
}

// ---------------- launch ---------------------------------------------------
extern "C" void kernel_launch(void* const* d_in, const int* in_sizes, int n_in,
                              void* d_out, int out_size)
{
    const float* x  = (const float*)d_in[0];
    const float* wq = (const float*)d_in[1];
    const float* bq = (const float*)d_in[2];
    const float* wk = (const float*)d_in[3];
    const float* bk = (const float*)d_in[4];
    const float* wv = (const float*)d_in[5];
    const float* bv = (const float*)d_in[6];
    const float* wo = (const float*)d_in[7];
    const float* bo = (const float*)d_in[8];
    float* out = (float*)d_out;

    cudaFuncSetAttribute(qkv_kernel,
                         cudaFuncAttributeMaxDynamicSharedMemorySize, GH_SMEM_BYTES);
    cudaFuncSetAttribute(out_kernel,
                         cudaFuncAttributeMaxDynamicSharedMemorySize, GH_SMEM_BYTES);

    convx_kernel<<<BT_ * C_ / 8 / 256, 256>>>(x);
    convw_kernel<<<dim3(C_ * C_ / 8 / 256, 4), 256>>>(wq, wk, wv, wo);
    qkv_kernel<<<dim3(C_ / 128, BT_ / 128, 3), 256, GH_SMEM_BYTES>>>(bq, bk, bv);
    flash_kernel<<<dim3(T_ / 256, B_ * H_), 256, FSMEM_BYTES>>>();
    out_kernel<<<dim3(C_ / 128, BT_ / 128), 256, GH_SMEM_BYTES>>>(bo, out);
}

// round 13
// speedup vs baseline: 1.0389x; 1.0389x over previous
#include <cuda_runtime.h>
#include <cuda_fp16.h>
#include <cstdint>
#include <math.h>

#define B_  2
#define T_  2048
#define C_  1024
#define H_  16
#define D_  64
#define BT_ 4096

// ---------------- scratch (allocation-free contract: __device__ globals) ----
__device__ __half g_qh[BT_ * C_];          // Q fp16 (rope+scale*log2e applied)
__device__ __half g_kh[BT_ * C_];          // K fp16 (rope applied)
__device__ __half g_vt[B_ * H_ * D_ * T_]; // V fp16 transposed [b][h][d][t]
__device__ __half g_atth[BT_ * C_];        // attention output, fp16
__device__ __half g_xh[BT_ * C_];          // x pre-rounded to fp16
__device__ __half g_wh[4 * C_ * C_];       // wq,wk,wv,wo pre-rounded to fp16

// ---------------- helpers ---------------------------------------------------
__device__ __forceinline__ uint32_t smem_u32(const void* p) {
    uint32_t a;
    asm("{ .reg .u64 t; cvta.to.shared.u64 t, %1; cvt.u32.u64 %0, t; }"
        : "=r"(a) : "l"(p));
    return a;
}

__device__ __forceinline__ float ex2f(float x) {
    float r;
    asm("ex2.approx.ftz.f32 %0, %1;" : "=f"(r) : "f"(x));
    return r;
}

__device__ __forceinline__ uint32_t packh2(float lo, float hi) {
    __half2 t = __floats2half2_rn(lo, hi);
    return *(uint32_t*)&t;
}

__device__ __forceinline__ void mma_f16r(float c[4], uint32_t a0, uint32_t a1,
                                         uint32_t a2, uint32_t a3,
                                         uint32_t b0, uint32_t b1) {
    asm volatile(
        "mma.sync.aligned.m16n8k16.row.col.f32.f16.f16.f32 "
        "{%0,%1,%2,%3}, {%4,%5,%6,%7}, {%8,%9}, {%0,%1,%2,%3};\n"
        : "+f"(c[0]), "+f"(c[1]), "+f"(c[2]), "+f"(c[3])
        : "r"(a0), "r"(a1), "r"(a2), "r"(a3), "r"(b0), "r"(b1));
}

#define LDSM_X4(r0, r1, r2, r3, addr) \
    asm volatile("ldmatrix.sync.aligned.m8n8.x4.shared.b16 {%0,%1,%2,%3}, [%4];" \
                 : "=r"(r0), "=r"(r1), "=r"(r2), "=r"(r3) : "r"(addr))

__device__ __forceinline__ void cpa16(uint32_t saddr, const void* g) {
    asm volatile("cp.async.cg.shared.global [%0], [%1], 16;"
                 :: "r"(saddr), "l"(g) : "memory");
}
#define CP_COMMIT() asm volatile("cp.async.commit_group;" ::: "memory")
#define CP_WAIT1()  asm volatile("cp.async.wait_group 1;" ::: "memory")
#define CP_WAIT0()  asm volatile("cp.async.wait_group 0;" ::: "memory")

__device__ __forceinline__ void rope2(float& e, float& o, float t,
                                      float f0, float f1, float scale) {
    float s0, c0, s1, c1;
    sincosf(t * f0, &s0, &c0);
    sincosf(t * f1, &s1, &c1);
    float en = (e * c0 - o * s0) * scale;
    float on = (o * c1 + e * s1) * scale;
    e = en; o = on;
}

#define ROPE_LG 0.41524103786091404f   // log2(10000)*2/64
#define QSCALE  0.18033688011112042f   // 0.125 * log2(e)

// ---------------- fp16 pre-convert kernels ---------------------------------
__global__ __launch_bounds__(256) void convx_kernel(const float* __restrict__ s)
{
    int i = blockIdx.x * 256 + threadIdx.x;
    float4 v0 = ((const float4*)s)[2 * i];
    float4 v1 = ((const float4*)s)[2 * i + 1];
    uint4 u;
    u.x = packh2(v0.x, v0.y); u.y = packh2(v0.z, v0.w);
    u.z = packh2(v1.x, v1.y); u.w = packh2(v1.z, v1.w);
    ((uint4*)g_xh)[i] = u;
}

__global__ __launch_bounds__(256) void convw_kernel(
    const float* __restrict__ wq, const float* __restrict__ wk,
    const float* __restrict__ wv, const float* __restrict__ wo)
{
    const float* src;
    int z = blockIdx.y;
    if (z == 0)      src = wq;
    else if (z == 1) src = wk;
    else if (z == 2) src = wv;
    else             src = wo;
    int i = blockIdx.x * 256 + threadIdx.x;
    float4 v0 = ((const float4*)src)[2 * i];
    float4 v1 = ((const float4*)src)[2 * i + 1];
    uint4 u;
    u.x = packh2(v0.x, v0.y); u.y = packh2(v0.z, v0.w);
    u.z = packh2(v1.x, v1.y); u.w = packh2(v1.z, v1.w);
    ((uint4*)(g_wh + (size_t)z * C_ * C_))[i] = u;
}

// ---------------- fp16 GEMM: C[M,N] = A[M,K] @ W[N,K]^T + bias --------------
// block 128x128, BK=64 halfs, 256 threads = 8 warps (warp tile 32m x 64n),
// m16n8k16, fragments via ldmatrix.x4 (stride 36 words: conflict-free).
#define GH_STR 36
#define GH_STAGE_W (2 * 128 * GH_STR)
#define GH_SMEM_BYTES (2 * GH_STAGE_W * 4)

__device__ __forceinline__ void gemm_f16_body(
    const __half* __restrict__ A, const __half* __restrict__ W,
    const float* __restrict__ bias, float* __restrict__ Cm,
    int bx, int by, int mode)
{
    extern __shared__ uint32_t gsm[];

    const int K = C_, N = C_;
    const int tid  = threadIdx.x;
    const int warp = tid >> 5;
    const int lane = tid & 31;
    const int g    = lane >> 2;
    const int tg   = lane & 3;
    const int m0   = (warp & 3) * 32;
    const int n0   = (warp >> 2) * 64;
    const int bm   = by * 128;
    const int bn   = bx * 128;

    const uint32_t smem_base = smem_u32(gsm);
    const __half* Ap = A + (size_t)bm * K;
    const __half* Wp = W + (size_t)bn * K;

    const int arow = (lane & 7) + ((lane >> 3) & 1) * 8;
    const int akof = (lane >> 4) * 4;
    const int brow = lane & 7;
    const int bkof = ((lane >> 3) & 1) * 4;
    const int bns  = (lane >> 4) * 8;

    float acc[2][8][4];
#pragma unroll
    for (int mt = 0; mt < 2; ++mt)
#pragma unroll
        for (int nt = 0; nt < 8; ++nt)
#pragma unroll
            for (int i = 0; i < 4; ++i) acc[mt][nt][i] = 0.f;

    auto issue = [&](int kb) {
        const int buf = kb & 1;
        uint32_t sa = smem_base + (buf * GH_STAGE_W) * 4;
        uint32_t sb = sa + 128 * GH_STR * 4;
        const __half* Ak = Ap + kb * 64;
        const __half* Wk = Wp + kb * 64;
#pragma unroll
        for (int i = 0; i < 4; ++i) {
            int id = tid + (i << 8);
            int r  = id >> 3;
            int c  = id & 7;
            cpa16(sa + (r * GH_STR + c * 4) * 4, Ak + (size_t)r * K + c * 8);
            cpa16(sb + (r * GH_STR + c * 4) * 4, Wk + (size_t)r * K + c * 8);
        }
    };

    issue(0);
    CP_COMMIT();

    const int NKB = K / 64;   // 16
    for (int kb = 0; kb < NKB; ++kb) {
        if (kb + 1 < NKB) {
            issue(kb + 1);
            CP_COMMIT();
            CP_WAIT1();
        } else {
            CP_WAIT0();
        }
        __syncthreads();

        const uint32_t As = smem_base + ((kb & 1) * GH_STAGE_W) * 4;
        const uint32_t Bs = As + 128 * GH_STR * 4;
        const uint32_t aAddr0 = As + ((m0 + arow) * GH_STR + akof) * 4;
        const uint32_t aAddr1 = As + ((m0 + 16 + arow) * GH_STR + akof) * 4;
        const uint32_t bAddr  = Bs + ((n0 + bns + brow) * GH_STR + bkof) * 4;

#pragma unroll
        for (int ks = 0; ks < 4; ++ks) {
            const int ko = ks * 8 * 4;
            uint32_t a[2][4], b[8][2];
            LDSM_X4(a[0][0], a[0][1], a[0][2], a[0][3], aAddr0 + ko);
            LDSM_X4(a[1][0], a[1][1], a[1][2], a[1][3], aAddr1 + ko);
#pragma unroll
            for (int ntp = 0; ntp < 4; ++ntp) {
                LDSM_X4(b[2 * ntp][0], b[2 * ntp][1],
                        b[2 * ntp + 1][0], b[2 * ntp + 1][1],
                        bAddr + (ntp * 16 * GH_STR) * 4 + ko);
            }
#pragma unroll
            for (int mt = 0; mt < 2; ++mt)
#pragma unroll
                for (int nt = 0; nt < 8; ++nt)
                    mma_f16r(acc[mt][nt], a[mt][0], a[mt][1], a[mt][2],
                             a[mt][3], b[nt][0], b[nt][1]);
        }
        __syncthreads();
    }

    // ---- epilogue ----------------------------------------------------------
    const bool do_rope = (mode == 1 || mode == 2);
    const float rscale = (mode == 1) ? QSCALE : 1.f;
#pragma unroll
    for (int nt = 0; nt < 8; ++nt) {
        int col = bn + n0 + nt * 8 + (tg << 1);
        float2 bv = *(const float2*)(bias + col);
        float f0 = 0.f, f1 = 0.f;
        if (do_rope) {
            int d0 = col & (D_ - 1);
            f0 = exp2f(-ROPE_LG * (float)(d0 & 31));
            f1 = exp2f(-ROPE_LG * (float)((d0 + 1) & 31));
        }
#pragma unroll
        for (int mt = 0; mt < 2; ++mt) {
            int row = bm + m0 + mt * 16 + g;
            float e0 = acc[mt][nt][0] + bv.x, o0 = acc[mt][nt][1] + bv.y;
            float e1 = acc[mt][nt][2] + bv.x, o1 = acc[mt][nt][3] + bv.y;
            if (do_rope) {
                rope2(e0, o0, (float)(row & (T_ - 1)), f0, f1, rscale);
                rope2(e1, o1, (float)((row + 8) & (T_ - 1)), f0, f1, rscale);
            }
            if (mode == 1 || mode == 2) {
                __half* dst = (mode == 1 ? g_qh : g_kh);
                *(__half2*)(dst + (size_t)row * N + col) =
                    __floats2half2_rn(e0, o0);
                *(__half2*)(dst + (size_t)(row + 8) * N + col) =
                    __floats2half2_rn(e1, o1);
            } else if (mode == 3) {
                int h = col >> 6, d = col & 63;
                int b = row >> 11;
                int t = row & (T_ - 1);
                __half* base = g_vt + ((size_t)(b * H_ + h) * D_) * T_;
                base[(size_t)d * T_ + t]            = __float2half_rn(e0);
                base[(size_t)(d + 1) * T_ + t]      = __float2half_rn(o0);
                base[(size_t)d * T_ + t + 8]        = __float2half_rn(e1);
                base[(size_t)(d + 1) * T_ + t + 8]  = __float2half_rn(o1);
            } else {
                *(float2*)(Cm + (size_t)row * N + col)       = make_float2(e0, o0);
                *(float2*)(Cm + (size_t)(row + 8) * N + col) = make_float2(e1, o1);
            }
        }
    }
}

__global__ __launch_bounds__(256, 2) void qkv_kernel(
    const float* __restrict__ bq, const float* __restrict__ bk,
    const float* __restrict__ bv)
{
    const float* bb; int mode;
    int z = blockIdx.z;
    if (z == 0)      { bb = bq; mode = 1; }
    else if (z == 1) { bb = bk; mode = 2; }
    else             { bb = bv; mode = 3; }
    gemm_f16_body(g_xh, g_wh + (size_t)z * C_ * C_, bb, nullptr,
                  blockIdx.x, blockIdx.y, mode);
}

__global__ __launch_bounds__(256, 2) void out_kernel(
    const float* __restrict__ bo, float* __restrict__ out)
{
    gemm_f16_body(g_atth, g_wh + (size_t)3 * C_ * C_, bo, out,
                  blockIdx.x, blockIdx.y, 0);
}

// ---------------- flash attention (fp16 m16n8k16, Br=128, 128 thr) ---------
// Round-11 body (ex2f softmax, ldmatrix K/V, FA2 P-fragment identity), but
// CTA halved: 4 warps x 32 q-rows, grid 512 -> 2 CTAs/SM (independent
// barrier domains + finer tail balance).
#define FSTR_W 36
#define F_STAGE_W (2 * 64 * FSTR_W)
#define FSMEM_BYTES (2 * F_STAGE_W * 4)

__global__ __launch_bounds__(128, 2) void flash_kernel()
{
    extern __shared__ uint32_t sm[];

    const int bh = blockIdx.y;
    const int b  = bh >> 4;
    const int h  = bh & 15;
    const int t0 = blockIdx.x << 7;                  // 128 q-rows per CTA
    const int tid  = threadIdx.x;
    const int warp = tid >> 5;
    const int lane = tid & 31;
    const int g    = lane >> 2;
    const int tg   = lane & 3;
    const int m0   = warp << 5;                      // 4 warps x 32 rows

    const uint32_t smem_base = smem_u32(sm);
    const __half* Kg0 = g_kh + (size_t)(b * T_) * C_ + h * D_;
    const __half* Vt0 = g_vt + (size_t)(b * H_ + h) * D_ * T_;

    const int brow = lane & 7;
    const int bkof = ((lane >> 3) & 1) * 4;
    const int bns  = (lane >> 4) * 8;
    const uint32_t bOffB = ((bns + brow) * FSTR_W + bkof) * 4;

    auto issue_kv = [&](int kt) {
        const int buf = kt & 1;
        const uint32_t kb = smem_base + (buf * F_STAGE_W) * 4;
        const uint32_t vb = kb + 64 * FSTR_W * 4;
#pragma unroll
        for (int i = 0; i < 4; ++i) {
            int id = tid + (i << 7);
            int r  = id >> 3;
            int c  = id & 7;
            cpa16(kb + (r * FSTR_W + c * 4) * 4,
                  Kg0 + (size_t)(kt * 64 + r) * C_ + c * 8);
            cpa16(vb + (r * FSTR_W + c * 4) * 4,
                  Vt0 + (size_t)r * T_ + kt * 64 + c * 8);
        }
    };

    issue_kv(0);
    CP_COMMIT();

    // ---- Q fragments, kt-invariant, direct from gmem into registers ------
    uint32_t qa[4][2][4];
    const __half* Qg = g_qh + (size_t)(b * T_ + t0 + m0) * C_ + h * D_;
#pragma unroll
    for (int ks = 0; ks < 4; ++ks)
#pragma unroll
        for (int mt = 0; mt < 2; ++mt) {
            const __half* p0 = Qg + (size_t)(mt * 16 + g) * C_ + 16 * ks + 2 * tg;
            const __half* p1 = p0 + 8 * C_;
            qa[ks][mt][0] = *(const uint32_t*)p0;
            qa[ks][mt][1] = *(const uint32_t*)p1;
            qa[ks][mt][2] = *(const uint32_t*)(p0 + 8);
            qa[ks][mt][3] = *(const uint32_t*)(p1 + 8);
        }

    float oacc[2][8][4];
    float m_r[4], l_r[4];
#pragma unroll
    for (int mt = 0; mt < 2; ++mt)
#pragma unroll
        for (int nt = 0; nt < 8; ++nt)
#pragma unroll
            for (int i = 0; i < 4; ++i) oacc[mt][nt][i] = 0.f;
#pragma unroll
    for (int i = 0; i < 4; ++i) { m_r[i] = -1e30f; l_r[i] = 0.f; }

    const int NKT = T_ / 64;   // 32
    for (int kt = 0; kt < NKT; ++kt) {
        if (kt + 1 < NKT) {
            issue_kv(kt + 1);
            CP_COMMIT();
            CP_WAIT1();
        } else {
            CP_WAIT0();
        }
        __syncthreads();

        const uint32_t KbA = smem_base + ((kt & 1) * F_STAGE_W) * 4 + bOffB;
        const uint32_t VbA = KbA + 64 * FSTR_W * 4;

        // ---- S = Q @ K^T (log2-scaled) ----
        float sacc[2][8][4];
#pragma unroll
        for (int mt = 0; mt < 2; ++mt)
#pragma unroll
            for (int nt = 0; nt < 8; ++nt)
#pragma unroll
                for (int i = 0; i < 4; ++i) sacc[mt][nt][i] = 0.f;

#pragma unroll
        for (int ks = 0; ks < 4; ++ks) {
            const int ko = ks * 8 * 4;
#pragma unroll
            for (int ntp = 0; ntp < 4; ++ntp) {
                uint32_t b00, b01, b10, b11;
                LDSM_X4(b00, b01, b10, b11,
                        KbA + (ntp * 16 * FSTR_W) * 4 + ko);
                mma_f16r(sacc[0][2 * ntp], qa[ks][0][0], qa[ks][0][1],
                         qa[ks][0][2], qa[ks][0][3], b00, b01);
                mma_f16r(sacc[1][2 * ntp], qa[ks][1][0], qa[ks][1][1],
                         qa[ks][1][2], qa[ks][1][3], b00, b01);
                mma_f16r(sacc[0][2 * ntp + 1], qa[ks][0][0], qa[ks][0][1],
                         qa[ks][0][2], qa[ks][0][3], b10, b11);
                mma_f16r(sacc[1][2 * ntp + 1], qa[ks][1][0], qa[ks][1][1],
                         qa[ks][1][2], qa[ks][1][3], b10, b11);
            }
        }

        // ---- online softmax (log2 domain) + pack P to fp16 A-fragments ----
        uint32_t pa[4][2][4];
#pragma unroll
        for (int mt = 0; mt < 2; ++mt) {
            float mx0 = -1e30f, mx1 = -1e30f;
#pragma unroll
            for (int nt = 0; nt < 8; ++nt) {
                mx0 = fmaxf(mx0, fmaxf(sacc[mt][nt][0], sacc[mt][nt][1]));
                mx1 = fmaxf(mx1, fmaxf(sacc[mt][nt][2], sacc[mt][nt][3]));
            }
            mx0 = fmaxf(mx0, __shfl_xor_sync(0xffffffffu, mx0, 1));
            mx0 = fmaxf(mx0, __shfl_xor_sync(0xffffffffu, mx0, 2));
            mx1 = fmaxf(mx1, __shfl_xor_sync(0xffffffffu, mx1, 1));
            mx1 = fmaxf(mx1, __shfl_xor_sync(0xffffffffu, mx1, 2));

            float mn0 = fmaxf(m_r[mt * 2 + 0], mx0);
            float mn1 = fmaxf(m_r[mt * 2 + 1], mx1);
            float corr0 = ex2f(m_r[mt * 2 + 0] - mn0);
            float corr1 = ex2f(m_r[mt * 2 + 1] - mn1);

            float rs0 = 0.f, rs1 = 0.f;
#pragma unroll
            for (int nt = 0; nt < 8; ++nt) {
                float p0 = ex2f(sacc[mt][nt][0] - mn0);
                float p1 = ex2f(sacc[mt][nt][1] - mn0);
                float p2 = ex2f(sacc[mt][nt][2] - mn1);
                float p3 = ex2f(sacc[mt][nt][3] - mn1);
                rs0 += p0 + p1;
                rs1 += p2 + p3;
                int ks = nt >> 1;
                int lo = (nt & 1) << 1;
                pa[ks][mt][lo + 0] = packh2(p0, p1);
                pa[ks][mt][lo + 1] = packh2(p2, p3);
            }
            rs0 += __shfl_xor_sync(0xffffffffu, rs0, 1);
            rs0 += __shfl_xor_sync(0xffffffffu, rs0, 2);
            rs1 += __shfl_xor_sync(0xffffffffu, rs1, 1);
            rs1 += __shfl_xor_sync(0xffffffffu, rs1, 2);

            l_r[mt * 2 + 0] = l_r[mt * 2 + 0] * corr0 + rs0;
            l_r[mt * 2 + 1] = l_r[mt * 2 + 1] * corr1 + rs1;
            m_r[mt * 2 + 0] = mn0;
            m_r[mt * 2 + 1] = mn1;

#pragma unroll
            for (int nt = 0; nt < 8; ++nt) {
                oacc[mt][nt][0] *= corr0; oacc[mt][nt][1] *= corr0;
                oacc[mt][nt][2] *= corr1; oacc[mt][nt][3] *= corr1;
            }
        }

        // ---- O += P @ V (V transposed tile: rows d, cols key) ----
#pragma unroll
        for (int ks = 0; ks < 4; ++ks) {
            const int ko = ks * 8 * 4;
#pragma unroll
            for (int ntp = 0; ntp < 4; ++ntp) {
                uint32_t b00, b01, b10, b11;
                LDSM_X4(b00, b01, b10, b11,
                        VbA + (ntp * 16 * FSTR_W) * 4 + ko);
                mma_f16r(oacc[0][2 * ntp], pa[ks][0][0], pa[ks][0][1],
                         pa[ks][0][2], pa[ks][0][3], b00, b01);
                mma_f16r(oacc[1][2 * ntp], pa[ks][1][0], pa[ks][1][1],
                         pa[ks][1][2], pa[ks][1][3], b00, b01);
                mma_f16r(oacc[0][2 * ntp + 1], pa[ks][0][0], pa[ks][0][1],
                         pa[ks][0][2], pa[ks][0][3], b10, b11);
                mma_f16r(oacc[1][2 * ntp + 1], pa[ks][1][0], pa[ks][1][1],
                         pa[ks][1][2], pa[ks][1][3], b10, b11);
            }
        }
        __syncthreads();
    }

    // ---- epilogue: normalize, write fp16 concat-head ----------------------
    __half* Og = g_atth + (size_t)(b * T_ + t0) * C_ + h * D_;
#pragma unroll
    for (int mt = 0; mt < 2; ++mt) {
        float inv0 = 1.f / l_r[mt * 2 + 0];
        float inv1 = 1.f / l_r[mt * 2 + 1];
        int row = m0 + mt * 16 + g;
#pragma unroll
        for (int nt = 0; nt < 8; ++nt) {
            int col = (nt << 3) + (tg << 1);
            *(__half2*)(Og + (size_t)row * C_ + col) =
                __floats2half2_rn(oacc[mt][nt][0] * inv0,
                                  oacc[mt][nt][1] * inv0);
            *(__half2*)(Og + (size_t)(row + 8) * C_ + col) =
                __floats2half2_rn(oacc[mt][nt][2] * inv1,
                                  oacc[mt][nt][3] * inv1);
        }
    }
}

// ---------------- launch ---------------------------------------------------
extern "C" void kernel_launch(void* const* d_in, const int* in_sizes, int n_in,
                              void* d_out, int out_size)
{
    const float* x  = (const float*)d_in[0];
    const float* wq = (const float*)d_in[1];
    const float* bq = (const float*)d_in[2];
    const float* wk = (const float*)d_in[3];
    const float* bk = (const float*)d_in[4];
    const float* wv = (const float*)d_in[5];
    const float* bv = (const float*)d_in[6];
    const float* wo = (const float*)d_in[7];
    const float* bo = (const float*)d_in[8];
    float* out = (float*)d_out;

    cudaFuncSetAttribute(qkv_kernel,
                         cudaFuncAttributeMaxDynamicSharedMemorySize, GH_SMEM_BYTES);
    cudaFuncSetAttribute(out_kernel,
                         cudaFuncAttributeMaxDynamicSharedMemorySize, GH_SMEM_BYTES);
    cudaFuncSetAttribute(flash_kernel,
                         cudaFuncAttributeMaxDynamicSharedMemorySize, FSMEM_BYTES);

    convx_kernel<<<BT_ * C_ / 8 / 256, 256>>>(x);
    convw_kernel<<<dim3(C_ * C_ / 8 / 256, 4), 256>>>(wq, wk, wv, wo);
    qkv_kernel<<<dim3(C_ / 128, BT_ / 128, 3), 256, GH_SMEM_BYTES>>>(bq, bk, bv);
    flash_kernel<<<dim3(T_ / 128, B_ * H_), 128, FSMEM_BYTES>>>();
    out_kernel<<<dim3(C_ / 128, BT_ / 128), 256, GH_SMEM_BYTES>>>(bo, out);
}